// round 2
// baseline (speedup 1.0000x reference)
#include <cuda_runtime.h>
#include <math.h>

#define NG     3200   // graphs = B*L
#define E      50     // nodes per graph
#define D      100    // embedding dim
#define H      100    // head dim
#define MT     16     // graphs per CTA in GEMM kernels (grid = 200)

// Scratch (no allocation allowed in kernel_launch)
__device__ __align__(16) float g_As[D * D];     // A^T: g_As[e*D+d] = sum_h Wk[d][h]*Wq[e][h]
__device__ __align__(16) float g_c[D];          // Wk @ bq
__device__ __align__(16) float g_bvs[H];        // bv + bs
__device__ __align__(16) float g_U[NG * D];     // per-graph u = A x0 + c
__device__ __align__(16) float g_wx[NG * 2 * D];// per-graph packed [w(100) | x0(100)]

// ---------------------------------------------------------------------------
// K1: precompute A^T, c, bv+bs.  grid = D+1 blocks x 128 threads.
// ---------------------------------------------------------------------------
__global__ void k_pre(const float* __restrict__ Wq, const float* __restrict__ bq,
                      const float* __restrict__ Wk,
                      const float* __restrict__ bv, const float* __restrict__ bs) {
    int e = blockIdx.x;
    int d = threadIdx.x;
    if (e < D) {
        __shared__ float wq[H];
        if (d < H) wq[d] = Wq[e * H + d];
        __syncthreads();
        if (d < D) {
            float acc = 0.f;
            #pragma unroll 4
            for (int h = 0; h < H; ++h) acc = fmaf(Wk[d * H + h], wq[h], acc);
            g_As[e * D + d] = acc;
        }
    } else {
        if (d < D) {
            float acc = 0.f;
            #pragma unroll 4
            for (int h = 0; h < H; ++h) acc = fmaf(Wk[d * H + h], bq[h], acc);
            g_c[d] = acc;
            g_bvs[d] = bv[d] + bs[d];
        }
    }
}

// ---------------------------------------------------------------------------
// K2: U[g][h] = c[h] + sum_e x0[g][e] * A^T[e][h]
// grid = NG/MT = 200 CTAs, 256 threads. A^T staged float4; x0 row-major smem.
// 200 compute threads (8 g-groups x 25 h-groups), each 2g x 4h, K=100.
// smem = 46.8KB -> 4 CTAs/SM.
// ---------------------------------------------------------------------------
__global__ __launch_bounds__(256) void k_u(const int* __restrict__ nid,
                                           const float* __restrict__ emb) {
    extern __shared__ float sm[];
    float* As = sm;                     // [D][D]
    float* xs = sm + D * D;             // [MT][D] row-major
    float* cs = sm + D * D + MT * D;    // [D]
    __shared__ int ids[MT];

    int tid   = threadIdx.x;
    int gbase = blockIdx.x * MT;

    for (int i = tid; i < D * D / 4; i += 256)
        reinterpret_cast<float4*>(As)[i] = reinterpret_cast<const float4*>(g_As)[i];
    if (tid < D)  cs[tid]  = g_c[tid];
    if (tid < MT) ids[tid] = nid[(gbase + tid) * E];
    __syncthreads();

    for (int q = tid; q < MT * (D / 4); q += 256) {
        int r = q / (D / 4), cc = q % (D / 4);
        reinterpret_cast<float4*>(&xs[r * D])[cc] =
            reinterpret_cast<const float4*>(emb)[ids[r] * (D / 4) + cc];
    }
    __syncthreads();

    if (tid < 200) {
        int ty = tid / 25, tx = tid % 25;
        int g0 = ty * 2,   h0 = tx * 4;
        float acc[2][4];
        #pragma unroll
        for (int i = 0; i < 2; ++i) {
            float4 b = *reinterpret_cast<const float4*>(&cs[h0]);
            acc[i][0] = b.x; acc[i][1] = b.y; acc[i][2] = b.z; acc[i][3] = b.w;
        }
        #pragma unroll 4
        for (int k = 0; k < D; ++k) {
            float x0v = xs[g0 * D + k];
            float x1v = xs[(g0 + 1) * D + k];
            float4 a = *reinterpret_cast<const float4*>(&As[k * D + h0]);
            acc[0][0] = fmaf(x0v, a.x, acc[0][0]);
            acc[0][1] = fmaf(x0v, a.y, acc[0][1]);
            acc[0][2] = fmaf(x0v, a.z, acc[0][2]);
            acc[0][3] = fmaf(x0v, a.w, acc[0][3]);
            acc[1][0] = fmaf(x1v, a.x, acc[1][0]);
            acc[1][1] = fmaf(x1v, a.y, acc[1][1]);
            acc[1][2] = fmaf(x1v, a.z, acc[1][2]);
            acc[1][3] = fmaf(x1v, a.w, acc[1][3]);
        }
        #pragma unroll
        for (int i = 0; i < 2; ++i) {
            float4 v = make_float4(acc[i][0], acc[i][1], acc[i][2], acc[i][3]);
            *reinterpret_cast<float4*>(&g_U[(gbase + g0 + i) * D + h0]) = v;
        }
    }
}

// ---------------------------------------------------------------------------
// K3: per-graph attention. one CTA per graph, 128 threads.
// gather X[50][100] (pad 101); scores = X@u/10 masked by adj[g][j][0];
// softmax; writes packed g_wx[g] = [w | x0].
// ---------------------------------------------------------------------------
__global__ __launch_bounds__(128) void k_attn(const int* __restrict__ nid,
                                              const int* __restrict__ adj,
                                              const float* __restrict__ emb) {
    constexpr int LD = 101;
    __shared__ float X[E * LD];
    __shared__ float u_s[D];
    __shared__ float sc[E];
    __shared__ float ps[E];
    __shared__ int ids[E];

    int g   = blockIdx.x;
    int tid = threadIdx.x;

    // independent loads issued up-front to overlap latency
    int m = 0;
    if (tid < E) {
        ids[tid] = nid[g * E + tid];
        m = adj[g * (E * E) + tid * E];   // edge j -> node 0
    }
    if (tid < D) u_s[tid] = g_U[g * D + tid];
    __syncthreads();

    for (int q = tid; q < E * (D / 4); q += 128) {
        int r = q / (D / 4), cc = q % (D / 4);
        float4 v = reinterpret_cast<const float4*>(emb)[ids[r] * (D / 4) + cc];
        float* dst = &X[r * LD + cc * 4];
        dst[0] = v.x; dst[1] = v.y; dst[2] = v.z; dst[3] = v.w;
    }
    __syncthreads();

    if (tid < E) {
        const float* xr = &X[tid * LD];
        float s = 0.f;
        #pragma unroll 4
        for (int d2 = 0; d2 < D; ++d2) s = fmaf(xr[d2], u_s[d2], s);
        sc[tid] = m ? s * 0.1f : -1e30f;   // /sqrt(H)
    }
    __syncthreads();

    float mx = -1e30f;
    #pragma unroll
    for (int j = 0; j < E; ++j) mx = fmaxf(mx, sc[j]);
    if (tid < E) ps[tid] = __expf(sc[tid] - mx);
    __syncthreads();

    float S = 0.f;
    #pragma unroll
    for (int j = 0; j < E; ++j) S += ps[j];
    float inv = 1.0f / S;  // node 0 self-loop -> S > 0

    if (tid < D) {
        float w = 0.f;
        #pragma unroll 2
        for (int j = 0; j < E; ++j) w = fmaf(ps[j], X[j * LD + tid], w);
        g_wx[g * (2 * D) + tid]     = w * inv;
        g_wx[g * (2 * D) + D + tid] = X[tid];   // x0 row
    }
}

// ---------------------------------------------------------------------------
// K4: out[g][h] = bvs[h] + sum_{k<200} g_wx[g][k] * Wc[k][h],
// Wc = [Wv ; Ws] stacked. grid = NG/MT = 200 CTAs, 256 threads.
// Input staging is a single coalesced linear copy (no gather).
// smem = 93.2KB -> 2 CTAs/SM.
// ---------------------------------------------------------------------------
__global__ __launch_bounds__(256) void k_out(const float* __restrict__ Wv,
                                             const float* __restrict__ Ws,
                                             float* __restrict__ out) {
    extern __shared__ float sm[];
    float* Wc  = sm;                         // [2D][H]
    float* smv = sm + 2 * D * H;             // [MT][2D] row-major
    float* bb  = sm + 2 * D * H + MT * 2 * D;// [H]

    int tid   = threadIdx.x;
    int gbase = blockIdx.x * MT;

    for (int i = tid; i < D * H / 4; i += 256)
        reinterpret_cast<float4*>(Wc)[i] = reinterpret_cast<const float4*>(Wv)[i];
    for (int i = tid; i < D * H / 4; i += 256)
        reinterpret_cast<float4*>(Wc)[D * H / 4 + i] = reinterpret_cast<const float4*>(Ws)[i];
    if (tid < H) bb[tid] = g_bvs[tid];
    // dense, fully coalesced copy of MT packed rows
    for (int q = tid; q < MT * (2 * D / 4); q += 256)
        reinterpret_cast<float4*>(smv)[q] =
            reinterpret_cast<const float4*>(g_wx)[gbase * (2 * D / 4) + q];
    __syncthreads();

    if (tid < 200) {
        int ty = tid / 25, tx = tid % 25;
        int g0 = ty * 2,   h0 = tx * 4;
        float acc[2][4];
        #pragma unroll
        for (int i = 0; i < 2; ++i) {
            float4 b = *reinterpret_cast<const float4*>(&bb[h0]);
            acc[i][0] = b.x; acc[i][1] = b.y; acc[i][2] = b.z; acc[i][3] = b.w;
        }
        #pragma unroll 4
        for (int k = 0; k < 2 * D; ++k) {
            float x0v = smv[g0 * (2 * D) + k];
            float x1v = smv[(g0 + 1) * (2 * D) + k];
            float4 wv = *reinterpret_cast<const float4*>(&Wc[k * H + h0]);
            acc[0][0] = fmaf(x0v, wv.x, acc[0][0]);
            acc[0][1] = fmaf(x0v, wv.y, acc[0][1]);
            acc[0][2] = fmaf(x0v, wv.z, acc[0][2]);
            acc[0][3] = fmaf(x0v, wv.w, acc[0][3]);
            acc[1][0] = fmaf(x1v, wv.x, acc[1][0]);
            acc[1][1] = fmaf(x1v, wv.y, acc[1][1]);
            acc[1][2] = fmaf(x1v, wv.z, acc[1][2]);
            acc[1][3] = fmaf(x1v, wv.w, acc[1][3]);
        }
        #pragma unroll
        for (int i = 0; i < 2; ++i) {
            float4 v = make_float4(acc[i][0], acc[i][1], acc[i][2], acc[i][3]);
            *reinterpret_cast<float4*>(&out[(gbase + g0 + i) * H + h0]) = v;
        }
    }
}

// ---------------------------------------------------------------------------
extern "C" void kernel_launch(void* const* d_in, const int* in_sizes, int n_in,
                              void* d_out, int out_size) {
    const int*   nid = (const int*)d_in[0];
    const int*   adj = (const int*)d_in[1];
    const float* emb = (const float*)d_in[2];
    const float* Wq  = (const float*)d_in[3];
    const float* bq  = (const float*)d_in[4];
    const float* Wk  = (const float*)d_in[5];
    // d_in[6] = bk: cancels in softmax (constant per-row shift)
    const float* Wv  = (const float*)d_in[7];
    const float* bv  = (const float*)d_in[8];
    const float* Ws  = (const float*)d_in[9];
    const float* bs  = (const float*)d_in[10];
    float* out = (float*)d_out;

    const int smem2 = (D * D + MT * D + D) * (int)sizeof(float);             // 46.8 KB
    const int smem4 = (2 * D * H + MT * 2 * D + H) * (int)sizeof(float);     // 93.2 KB
    cudaFuncSetAttribute(k_u,   cudaFuncAttributeMaxDynamicSharedMemorySize, smem2);
    cudaFuncSetAttribute(k_out, cudaFuncAttributeMaxDynamicSharedMemorySize, smem4);

    k_pre<<<D + 1, 128>>>(Wq, bq, Wk, bv, bs);
    k_u<<<NG / MT, 256, smem2>>>(nid, emb);
    k_attn<<<NG, 128>>>(nid, adj, emb);
    k_out<<<NG / MT, 256, smem4>>>(Wv, Ws, out);
}

// round 3
// speedup vs baseline: 1.2242x; 1.2242x over previous
#include <cuda_runtime.h>
#include <math.h>

#define NG  3200   // graphs = B*L
#define E   50     // nodes per graph
#define D   100    // embedding dim
#define H   100    // head dim
#define NP  128    // padded H for weight tiles (power of 2)
#define MG  8      // graphs per GEMM tile

// Scratch (no allocation allowed in kernel_launch)
__device__ __align__(16) float g_As[D * D];      // A^T: [e][d] = sum_h Wk[d][h]*Wq[e][h]
__device__ __align__(16) float g_c[D];           // Wk @ bq
__device__ __align__(16) float g_bvs[H];         // bv + bs
__device__ __align__(16) float g_U[NG * D];      // per-graph u = A x0 + c
__device__ __align__(16) float g_wx[NG * 2 * D]; // per-graph packed [w(100) | x0(100)]

// ---------------------------------------------------------------------------
// K1: precompute A^T, c, bv+bs.  grid = D+1 blocks x 128 threads.
// ---------------------------------------------------------------------------
__global__ void k_pre(const float* __restrict__ Wq, const float* __restrict__ bq,
                      const float* __restrict__ Wk,
                      const float* __restrict__ bv, const float* __restrict__ bs) {
    int e = blockIdx.x;
    int d = threadIdx.x;
    if (e < D) {
        __shared__ float wq[H];
        if (d < H) wq[d] = Wq[e * H + d];
        __syncthreads();
        if (d < D) {
            float acc = 0.f;
            #pragma unroll 4
            for (int h = 0; h < H; ++h) acc = fmaf(Wk[d * H + h], wq[h], acc);
            g_As[e * D + d] = acc;
        }
    } else {
        if (d < D) {
            float acc = 0.f;
            #pragma unroll 4
            for (int h = 0; h < H; ++h) acc = fmaf(Wk[d * H + h], bq[h], acc);
            g_c[d] = acc;
            g_bvs[d] = bv[d] + bs[d];
        }
    }
}

// ---------------------------------------------------------------------------
// K2: U[g] = c + A x0[g].  Persistent-strided: grid=296, tiles of MG=8 graphs.
// A staged once per CTA as [D][NP] zero-padded.  x tile k-major [D][9].
// lane = (gi:3, hgrp:2); each thread: 1 graph x 4 h, weight loads broadcast.
// ---------------------------------------------------------------------------
__global__ __launch_bounds__(256) void k_u(const int* __restrict__ nid,
                                           const float* __restrict__ emb) {
    extern __shared__ float sm[];
    float* A  = sm;            // [D][NP]
    float* cs = sm + D * NP;   // [NP]
    float* xt = cs + NP;       // [D][9] k-major tile (pad 9: bank-clean)
    __shared__ int ids[MG];

    int tid = threadIdx.x;
    for (int i = tid; i < D * NP; i += 256) {
        int k = i >> 7, h = i & (NP - 1);
        A[i] = (h < H) ? g_As[k * D + h] : 0.f;
    }
    if (tid < NP) cs[tid] = (tid < H) ? g_c[tid] : 0.f;

    int lane = tid & 31, wid = tid >> 5;
    int gi = lane & 7, hgrp = lane >> 3;
    int h0 = wid * 16 + hgrp * 4;

    int ntiles = NG / MG;  // 400
    for (int t = blockIdx.x; t < ntiles; t += gridDim.x) {
        int gbase = t * MG;
        __syncthreads();
        if (tid < MG) ids[tid] = nid[(gbase + tid) * E];
        __syncthreads();
        for (int q = tid; q < MG * (D / 4); q += 256) {  // 200 float4
            int r = q & 7, cc = q >> 3;
            float4 v = reinterpret_cast<const float4*>(emb)[ids[r] * (D / 4) + cc];
            xt[(cc * 4 + 0) * 9 + r] = v.x;
            xt[(cc * 4 + 1) * 9 + r] = v.y;
            xt[(cc * 4 + 2) * 9 + r] = v.z;
            xt[(cc * 4 + 3) * 9 + r] = v.w;
        }
        __syncthreads();
        float4 b = *reinterpret_cast<const float4*>(&cs[h0]);
        float a0 = b.x, a1 = b.y, a2 = b.z, a3 = b.w;
        #pragma unroll 4
        for (int k = 0; k < D; ++k) {
            float xv = xt[k * 9 + gi];
            float4 w = *reinterpret_cast<const float4*>(&A[k * NP + h0]);
            a0 = fmaf(xv, w.x, a0); a1 = fmaf(xv, w.y, a1);
            a2 = fmaf(xv, w.z, a2); a3 = fmaf(xv, w.w, a3);
        }
        if (h0 < H)
            *reinterpret_cast<float4*>(&g_U[(gbase + gi) * D + h0]) =
                make_float4(a0, a1, a2, a3);
    }
}

// ---------------------------------------------------------------------------
// K3: per-graph attention with mask compaction. one CTA per graph, 128 thr.
// Rows with adj[g][j][0]==0 are fully dropped (masked from softmax AND sum).
// Node 0 self-loop guaranteed -> compact row 0 == x0.
// ---------------------------------------------------------------------------
__global__ __launch_bounds__(128) void k_attn(const int* __restrict__ nid,
                                              const int* __restrict__ adj,
                                              const float* __restrict__ emb) {
    constexpr int LD = 101;
    __shared__ float X[E * LD];
    __shared__ float u_s[D];
    __shared__ float sc[E];
    __shared__ float ps[E];
    __shared__ int ids[E];
    __shared__ int msk[E];
    __shared__ int cnt_s;

    int g = blockIdx.x, tid = threadIdx.x;

    if (tid < E) {
        ids[tid] = nid[g * E + tid];
        msk[tid] = adj[g * (E * E) + tid * E];  // edge j -> node 0
    }
    if (tid < D) u_s[tid] = g_U[g * D + tid];
    __syncthreads();

    if (tid == 0) {  // deterministic in-place compaction (c <= j always)
        int c = 0;
        for (int j = 0; j < E; ++j)
            if (msk[j]) ids[c++] = ids[j];
        cnt_s = c;
    }
    __syncthreads();
    int cnt = cnt_s;

    for (int q = tid; q < cnt * (D / 4); q += 128) {
        int r = q / 25, cc = q % 25;
        float4 v = reinterpret_cast<const float4*>(emb)[ids[r] * (D / 4) + cc];
        float* dst = &X[r * LD + cc * 4];
        dst[0] = v.x; dst[1] = v.y; dst[2] = v.z; dst[3] = v.w;
    }
    __syncthreads();

    if (tid < cnt) {
        const float* xr = &X[tid * LD];
        float s0 = 0.f, s1 = 0.f;
        #pragma unroll 10
        for (int d2 = 0; d2 < D; d2 += 2) {
            s0 = fmaf(xr[d2],     u_s[d2],     s0);
            s1 = fmaf(xr[d2 + 1], u_s[d2 + 1], s1);
        }
        sc[tid] = (s0 + s1) * 0.1f;  // /sqrt(H)
    }
    __syncthreads();

    float mx = -1e30f;
    for (int j = 0; j < cnt; ++j) mx = fmaxf(mx, sc[j]);
    if (tid < cnt) ps[tid] = __expf(sc[tid] - mx);
    __syncthreads();

    float S = 0.f;
    for (int j = 0; j < cnt; ++j) S += ps[j];
    float inv = 1.0f / S;

    if (tid < D) {
        float w = 0.f;
        for (int j = 0; j < cnt; ++j) w = fmaf(ps[j], X[j * LD + tid], w);
        g_wx[g * (2 * D) + tid]     = w * inv;
        g_wx[g * (2 * D) + D + tid] = X[tid];  // compact row 0 = x0
    }
}

// ---------------------------------------------------------------------------
// K4: out[g] = bvs + [w|x0] @ [Wv;Ws].  Same persistent broadcast-weight GEMM,
// K=200.  grid=296 (2 CTAs/SM at 107.5KB smem).
// ---------------------------------------------------------------------------
__global__ __launch_bounds__(256) void k_out(const float* __restrict__ Wv,
                                             const float* __restrict__ Ws,
                                             float* __restrict__ out) {
    extern __shared__ float sm[];
    float* Wc = sm;                // [2D][NP]
    float* bb = sm + 2 * D * NP;   // [NP]
    float* xt = bb + NP;           // [2D][9]

    int tid = threadIdx.x;
    for (int i = tid; i < 2 * D * NP; i += 256) {
        int k = i >> 7, h = i & (NP - 1);
        float v = 0.f;
        if (h < H) v = (k < D) ? Wv[k * H + h] : Ws[(k - D) * H + h];
        Wc[i] = v;
    }
    if (tid < NP) bb[tid] = (tid < H) ? g_bvs[tid] : 0.f;

    int lane = tid & 31, wid = tid >> 5;
    int gi = lane & 7, hgrp = lane >> 3;
    int h0 = wid * 16 + hgrp * 4;

    int ntiles = NG / MG;  // 400
    for (int t = blockIdx.x; t < ntiles; t += gridDim.x) {
        int gbase = t * MG;
        __syncthreads();
        for (int q = tid; q < MG * (2 * D / 4); q += 256) {  // 400 float4
            int r = q & 7, cc = q >> 3;
            float4 v = reinterpret_cast<const float4*>(g_wx)[(gbase + r) * (2 * D / 4) + cc];
            xt[(cc * 4 + 0) * 9 + r] = v.x;
            xt[(cc * 4 + 1) * 9 + r] = v.y;
            xt[(cc * 4 + 2) * 9 + r] = v.z;
            xt[(cc * 4 + 3) * 9 + r] = v.w;
        }
        __syncthreads();
        float4 b = *reinterpret_cast<const float4*>(&bb[h0]);
        float a0 = b.x, a1 = b.y, a2 = b.z, a3 = b.w;
        #pragma unroll 4
        for (int k = 0; k < 2 * D; ++k) {
            float xv = xt[k * 9 + gi];
            float4 w = *reinterpret_cast<const float4*>(&Wc[k * NP + h0]);
            a0 = fmaf(xv, w.x, a0); a1 = fmaf(xv, w.y, a1);
            a2 = fmaf(xv, w.z, a2); a3 = fmaf(xv, w.w, a3);
        }
        if (h0 < H)
            *reinterpret_cast<float4*>(&out[(gbase + gi) * H + h0]) =
                make_float4(a0, a1, a2, a3);
    }
}

// ---------------------------------------------------------------------------
extern "C" void kernel_launch(void* const* d_in, const int* in_sizes, int n_in,
                              void* d_out, int out_size) {
    const int*   nid = (const int*)d_in[0];
    const int*   adj = (const int*)d_in[1];
    const float* emb = (const float*)d_in[2];
    const float* Wq  = (const float*)d_in[3];
    const float* bq  = (const float*)d_in[4];
    const float* Wk  = (const float*)d_in[5];
    // d_in[6] = bk: cancels in softmax (constant per-row shift)
    const float* Wv  = (const float*)d_in[7];
    const float* bv  = (const float*)d_in[8];
    const float* Ws  = (const float*)d_in[9];
    const float* bs  = (const float*)d_in[10];
    float* out = (float*)d_out;

    const int smemU = (D * NP + NP + D * 9) * (int)sizeof(float);          // ~54KB
    const int smemO = (2 * D * NP + NP + 2 * D * 9) * (int)sizeof(float);  // ~107.5KB
    cudaFuncSetAttribute(k_u,   cudaFuncAttributeMaxDynamicSharedMemorySize, smemU);
    cudaFuncSetAttribute(k_out, cudaFuncAttributeMaxDynamicSharedMemorySize, smemO);

    k_pre<<<D + 1, 128>>>(Wq, bq, Wk, bv, bs);
    k_u<<<296, 256, smemU>>>(nid, emb);
    k_attn<<<NG, 128>>>(nid, adj, emb);
    k_out<<<296, 256, smemO>>>(Wv, Ws, out);
}

// round 4
// speedup vs baseline: 1.5359x; 1.2546x over previous
#include <cuda_runtime.h>
#include <math.h>

#define NG  3200   // graphs = B*L
#define E   50     // nodes per graph
#define D   100    // embedding dim
#define H   100    // head dim
#define NP  128    // padded column count for weight tiles

// Scratch (no allocation allowed in kernel_launch)
__device__ __align__(16) float g_Ap[D * NP];      // padded A: u[d] = sum_e x0[e]*g_Ap[e*NP+d]
__device__ __align__(16) float g_cp[NP];          // padded  Wk @ bq
__device__ __align__(16) float g_bp[NP];          // padded  bv + bs
__device__ __align__(16) float g_Wcp[2 * D * NP]; // padded  [Wv ; Ws]
__device__ __align__(16) float g_U[NG * D];       // per-graph u
__device__ __align__(16) float g_wx[NG * 2 * D];  // per-graph packed [w(100) | x0(100)]

// ---------------------------------------------------------------------------
// K1: precompute padded A, c, bvs, Wc.  grid = 301 blocks x 128 threads.
//   blocks 0..99   : row e of A (100-dot per element)
//   block  100     : padded c and bvs
//   blocks 101..300: row k of Wc = [Wv;Ws] zero-padded to 128 cols
// ---------------------------------------------------------------------------
__global__ void k_pre(const float* __restrict__ Wq, const float* __restrict__ bq,
                      const float* __restrict__ Wk,
                      const float* __restrict__ Wv, const float* __restrict__ bv,
                      const float* __restrict__ Ws, const float* __restrict__ bs) {
    int b = blockIdx.x;
    int d = threadIdx.x;
    if (b < D) {                         // A[e=b][d] = sum_h Wk[d][h] * Wq[e][h]
        __shared__ float wq[H];
        if (d < H) wq[d] = Wq[b * H + d];
        __syncthreads();
        if (d < NP) {
            float acc = 0.f;
            if (d < D) {
                #pragma unroll 4
                for (int h = 0; h < H; ++h) acc = fmaf(Wk[d * H + h], wq[h], acc);
            }
            g_Ap[b * NP + d] = acc;
        }
    } else if (b == D) {
        if (d < NP) {
            float c = 0.f, bb = 0.f;
            if (d < D) {
                #pragma unroll 4
                for (int h = 0; h < H; ++h) c = fmaf(Wk[d * H + h], bq[h], c);
                bb = bv[d] + bs[d];
            }
            g_cp[d] = c;
            g_bp[d] = bb;
        }
    } else {                             // Wc row k = b-101
        int k = b - (D + 1);
        if (d < NP) {
            float v = 0.f;
            if (d < H) v = (k < D) ? Wv[k * H + d] : Ws[(k - D) * H + d];
            g_Wcp[k * NP + d] = v;
        }
    }
}

// ---------------------------------------------------------------------------
// K2: U[g] = c + A x0[g].  grid=400, 256 thr. warp = 1 graph x 128 padded h.
// x0 rows staged to smem (warp-uniform reads); A read via LDG.128 (L1-hot).
// ---------------------------------------------------------------------------
__global__ __launch_bounds__(256) void k_u(const int* __restrict__ nid,
                                           const float* __restrict__ emb) {
    __shared__ float xs[8][D];
    __shared__ int ids[8];
    int tid = threadIdx.x, warp = tid >> 5, lane = tid & 31;
    int gbase = blockIdx.x * 8;

    if (tid < 8) ids[tid] = nid[(gbase + tid) * E];
    __syncthreads();
    if (tid < 8 * (D / 4)) {             // 200 float4, coalesced per row
        int r = tid / 25, c = tid % 25;
        reinterpret_cast<float4*>(&xs[r][0])[c] =
            reinterpret_cast<const float4*>(emb)[ids[r] * (D / 4) + c];
    }
    __syncthreads();

    int h0 = lane * 4;
    float4 acc = reinterpret_cast<const float4*>(g_cp)[lane];
    const float* xr = xs[warp];
    #pragma unroll 5
    for (int k = 0; k < D; k += 4) {
        float4 xv = *reinterpret_cast<const float4*>(&xr[k]);   // uniform bcast
        float4 w0 = *reinterpret_cast<const float4*>(&g_Ap[(k + 0) * NP + h0]);
        float4 w1 = *reinterpret_cast<const float4*>(&g_Ap[(k + 1) * NP + h0]);
        float4 w2 = *reinterpret_cast<const float4*>(&g_Ap[(k + 2) * NP + h0]);
        float4 w3 = *reinterpret_cast<const float4*>(&g_Ap[(k + 3) * NP + h0]);
        acc.x = fmaf(xv.x, w0.x, acc.x); acc.y = fmaf(xv.x, w0.y, acc.y);
        acc.z = fmaf(xv.x, w0.z, acc.z); acc.w = fmaf(xv.x, w0.w, acc.w);
        acc.x = fmaf(xv.y, w1.x, acc.x); acc.y = fmaf(xv.y, w1.y, acc.y);
        acc.z = fmaf(xv.y, w1.z, acc.z); acc.w = fmaf(xv.y, w1.w, acc.w);
        acc.x = fmaf(xv.z, w2.x, acc.x); acc.y = fmaf(xv.z, w2.y, acc.y);
        acc.z = fmaf(xv.z, w2.z, acc.z); acc.w = fmaf(xv.z, w2.w, acc.w);
        acc.x = fmaf(xv.w, w3.x, acc.x); acc.y = fmaf(xv.w, w3.y, acc.y);
        acc.z = fmaf(xv.w, w3.z, acc.z); acc.w = fmaf(xv.w, w3.w, acc.w);
    }
    if (h0 < H)
        *reinterpret_cast<float4*>(&g_U[(gbase + warp) * D + h0]) = acc;
}

// ---------------------------------------------------------------------------
// K3: per-graph attention with mask compaction. one CTA per graph, 128 thr.
// Rows with adj[g][j][0]==0 dropped entirely; node-0 self-loop guaranteed.
// Writes packed g_wx[g] = [w | x0].
// ---------------------------------------------------------------------------
__global__ __launch_bounds__(128) void k_attn(const int* __restrict__ nid,
                                              const int* __restrict__ adj,
                                              const float* __restrict__ emb) {
    constexpr int LD = 101;
    __shared__ float X[E * LD];
    __shared__ float u_s[D];
    __shared__ float sc[E];
    __shared__ float ps[E];
    __shared__ int ids[E];
    __shared__ int msk[E];
    __shared__ int cnt_s;

    int g = blockIdx.x, tid = threadIdx.x;

    if (tid < E) {
        ids[tid] = nid[g * E + tid];
        msk[tid] = adj[g * (E * E) + tid * E];  // edge j -> node 0
    }
    if (tid < D) u_s[tid] = g_U[g * D + tid];
    __syncthreads();

    if (tid == 0) {                     // deterministic in-place compaction
        int c = 0;
        for (int j = 0; j < E; ++j)
            if (msk[j]) ids[c++] = ids[j];
        cnt_s = c;
    }
    __syncthreads();
    int cnt = cnt_s;

    for (int q = tid; q < cnt * (D / 4); q += 128) {
        int r = q / 25, cc = q % 25;
        float4 v = reinterpret_cast<const float4*>(emb)[ids[r] * (D / 4) + cc];
        float* dst = &X[r * LD + cc * 4];
        dst[0] = v.x; dst[1] = v.y; dst[2] = v.z; dst[3] = v.w;
    }
    __syncthreads();

    if (tid < cnt) {
        const float* xr = &X[tid * LD];
        float s0 = 0.f, s1 = 0.f;
        #pragma unroll 10
        for (int d2 = 0; d2 < D; d2 += 2) {
            s0 = fmaf(xr[d2],     u_s[d2],     s0);
            s1 = fmaf(xr[d2 + 1], u_s[d2 + 1], s1);
        }
        sc[tid] = (s0 + s1) * 0.1f;     // /sqrt(H)
    }
    __syncthreads();

    float mx = -1e30f;
    for (int j = 0; j < cnt; ++j) mx = fmaxf(mx, sc[j]);
    if (tid < cnt) ps[tid] = __expf(sc[tid] - mx);
    __syncthreads();

    float S = 0.f;
    for (int j = 0; j < cnt; ++j) S += ps[j];
    float inv = 1.0f / S;

    if (tid < D) {
        float w = 0.f;
        for (int j = 0; j < cnt; ++j) w = fmaf(ps[j], X[j * LD + tid], w);
        g_wx[g * (2 * D) + tid]     = w * inv;
        g_wx[g * (2 * D) + D + tid] = X[tid];   // compact row 0 = x0
    }
}

// ---------------------------------------------------------------------------
// K4: out[g] = bvs + [w|x0] @ [Wv;Ws].  grid=400, 256 thr.
// warp = 1 graph x 128 padded h; K=200; weights from L1 via LDG.128.
// ---------------------------------------------------------------------------
__global__ __launch_bounds__(256) void k_out(float* __restrict__ out) {
    __shared__ float xs[8][2 * D];
    int tid = threadIdx.x, warp = tid >> 5, lane = tid & 31;
    int gbase = blockIdx.x * 8;

    for (int q = tid; q < 8 * (2 * D / 4); q += 256) {   // 400 float4, coalesced
        int r = q / 50, c = q % 50;
        reinterpret_cast<float4*>(&xs[r][0])[c] =
            reinterpret_cast<const float4*>(g_wx)[(gbase + r) * (2 * D / 4) + c];
    }
    __syncthreads();

    int h0 = lane * 4;
    float4 acc = reinterpret_cast<const float4*>(g_bp)[lane];
    const float* xr = xs[warp];
    #pragma unroll 5
    for (int k = 0; k < 2 * D; k += 4) {
        float4 xv = *reinterpret_cast<const float4*>(&xr[k]);   // uniform bcast
        float4 w0 = *reinterpret_cast<const float4*>(&g_Wcp[(k + 0) * NP + h0]);
        float4 w1 = *reinterpret_cast<const float4*>(&g_Wcp[(k + 1) * NP + h0]);
        float4 w2 = *reinterpret_cast<const float4*>(&g_Wcp[(k + 2) * NP + h0]);
        float4 w3 = *reinterpret_cast<const float4*>(&g_Wcp[(k + 3) * NP + h0]);
        acc.x = fmaf(xv.x, w0.x, acc.x); acc.y = fmaf(xv.x, w0.y, acc.y);
        acc.z = fmaf(xv.x, w0.z, acc.z); acc.w = fmaf(xv.x, w0.w, acc.w);
        acc.x = fmaf(xv.y, w1.x, acc.x); acc.y = fmaf(xv.y, w1.y, acc.y);
        acc.z = fmaf(xv.y, w1.z, acc.z); acc.w = fmaf(xv.y, w1.w, acc.w);
        acc.x = fmaf(xv.z, w2.x, acc.x); acc.y = fmaf(xv.z, w2.y, acc.y);
        acc.z = fmaf(xv.z, w2.z, acc.z); acc.w = fmaf(xv.z, w2.w, acc.w);
        acc.x = fmaf(xv.w, w3.x, acc.x); acc.y = fmaf(xv.w, w3.y, acc.y);
        acc.z = fmaf(xv.w, w3.z, acc.z); acc.w = fmaf(xv.w, w3.w, acc.w);
    }
    if (h0 < H)
        *reinterpret_cast<float4*>(&out[(gbase + warp) * H + h0]) = acc;
}

// ---------------------------------------------------------------------------
extern "C" void kernel_launch(void* const* d_in, const int* in_sizes, int n_in,
                              void* d_out, int out_size) {
    const int*   nid = (const int*)d_in[0];
    const int*   adj = (const int*)d_in[1];
    const float* emb = (const float*)d_in[2];
    const float* Wq  = (const float*)d_in[3];
    const float* bq  = (const float*)d_in[4];
    const float* Wk  = (const float*)d_in[5];
    // d_in[6] = bk: cancels in softmax (constant per-row shift)
    const float* Wv  = (const float*)d_in[7];
    const float* bv  = (const float*)d_in[8];
    const float* Ws  = (const float*)d_in[9];
    const float* bs  = (const float*)d_in[10];
    float* out = (float*)d_out;

    k_pre<<<3 * D + 1, 128>>>(Wq, bq, Wk, Wv, bv, Ws, bs);
    k_u<<<NG / 8, 256>>>(nid, emb);
    k_attn<<<NG, 128>>>(nid, adj, emb);
    k_out<<<NG / 8, 256>>>(out);
}

// round 6
// speedup vs baseline: 1.6846x; 1.0968x over previous
#include <cuda_runtime.h>
#include <math.h>

#define NG  3200   // graphs = B*L
#define E   50     // nodes per graph
#define D   100    // embedding dim
#define H   100    // head dim
#define NP  128    // padded column count for weight tiles

// Scratch (no allocation allowed in kernel_launch)
__device__ __align__(16) float g_Ap[D * NP];      // padded A: u[d]=sum_e x0[e]*g_Ap[e*NP+d]
__device__ __align__(16) float g_cp[NP];          // padded Wk @ bq
__device__ __align__(16) float g_bp[NP];          // padded bv + bs
__device__ __align__(16) float g_Wcp[2 * D * NP]; // padded [Wv ; Ws]
__device__ __align__(16) float g_U[NG * D];       // per-graph u
__device__ __align__(16) float g_wx[NG * 2 * D];  // per-graph packed [w(100) | x0(100)]

// ---------------------------------------------------------------------------
// K1: precompute padded A, c, bvs, Wc.  grid = 3D+1 blocks x 128 threads.
// ---------------------------------------------------------------------------
__global__ void k_pre(const float* __restrict__ Wq, const float* __restrict__ bq,
                      const float* __restrict__ Wk,
                      const float* __restrict__ Wv, const float* __restrict__ bv,
                      const float* __restrict__ Ws, const float* __restrict__ bs) {
    int b = blockIdx.x;
    int d = threadIdx.x;
    if (b < D) {                         // A[e=b][d] = sum_h Wk[d][h] * Wq[e][h]
        __shared__ float wq[H];
        if (d < H) wq[d] = Wq[b * H + d];
        __syncthreads();
        if (d < NP) {
            float acc = 0.f;
            if (d < D) {
                #pragma unroll 4
                for (int h = 0; h < H; ++h) acc = fmaf(Wk[d * H + h], wq[h], acc);
            }
            g_Ap[b * NP + d] = acc;
        }
    } else if (b == D) {
        if (d < NP) {
            float c = 0.f, bb = 0.f;
            if (d < D) {
                #pragma unroll 4
                for (int h = 0; h < H; ++h) c = fmaf(Wk[d * H + h], bq[h], c);
                bb = bv[d] + bs[d];
            }
            g_cp[d] = c;
            g_bp[d] = bb;
        }
    } else {                             // Wc row k = b - (D+1)
        int k = b - (D + 1);
        if (d < NP) {
            float v = 0.f;
            if (d < H) v = (k < D) ? Wv[k * H + d] : Ws[(k - D) * H + d];
            g_Wcp[k * NP + d] = v;
        }
    }
}

// ---------------------------------------------------------------------------
// K2: U[g] = c + A x0[g].  grid=400, 256 thr (8 warps, 8 graphs per CTA).
// warp = 4 graphs x 32 cols: lane = g_local*8 + hgrp; cols ct*32 + hgrp*4.
// Weight float4s span 128B per warp per k -> 1 L1 wavefront, shared 4 ways.
// ---------------------------------------------------------------------------
__global__ __launch_bounds__(256) void k_u(const int* __restrict__ nid,
                                           const float* __restrict__ emb) {
    __shared__ float xs[8][D];
    __shared__ int ids[8];
    int tid = threadIdx.x, warp = tid >> 5, lane = tid & 31;
    int gbase = blockIdx.x * 8;

    if (tid < 8) ids[tid] = nid[(gbase + tid) * E];
    __syncthreads();
    if (tid < 8 * (D / 4)) {             // 200 float4, coalesced per row
        int r = tid / 25, c = tid % 25;
        reinterpret_cast<float4*>(&xs[r][0])[c] =
            reinterpret_cast<const float4*>(emb)[ids[r] * (D / 4) + c];
    }
    __syncthreads();

    int gg = (warp >> 2) * 4;            // graph group: 0 or 4
    int ct = warp & 3;                   // col tile: cols ct*32..ct*32+31
    int gl = lane >> 3;                  // graph within group
    int hg = lane & 7;
    int h0 = ct * 32 + hg * 4;
    const float* xr = xs[gg + gl];

    float4 acc = *reinterpret_cast<const float4*>(&g_cp[h0]);
    #pragma unroll 4
    for (int k = 0; k < D; ++k) {
        float  xv = xr[k];                                        // 4-way bcast
        float4 w  = *reinterpret_cast<const float4*>(&g_Ap[k * NP + h0]);
        acc.x = fmaf(xv, w.x, acc.x); acc.y = fmaf(xv, w.y, acc.y);
        acc.z = fmaf(xv, w.z, acc.z); acc.w = fmaf(xv, w.w, acc.w);
    }
    if (h0 < H)
        *reinterpret_cast<float4*>(&g_U[(gbase + gg + gl) * D + h0]) = acc;
}

// ---------------------------------------------------------------------------
// K3: per-graph attention, parallel ballot compaction. 1 CTA/graph, 128 thr.
// Rows with adj[g][j][0]==0 dropped entirely; node-0 self-loop guaranteed.
// Writes packed g_wx[g] = [w | x0].
// ---------------------------------------------------------------------------
__global__ __launch_bounds__(128) void k_attn(const int* __restrict__ nid,
                                              const int* __restrict__ adj,
                                              const float* __restrict__ emb) {
    constexpr int LD = 101;
    __shared__ float X[E * LD];
    __shared__ float u_s[D];
    __shared__ float sc[E];
    __shared__ float ps[E];
    __shared__ int ids[E];
    __shared__ unsigned bal[2];
    __shared__ int cnt_s;

    int g = blockIdx.x, tid = threadIdx.x;
    int warp = tid >> 5, lane = tid & 31;

    int myid = 0, m = 0;
    if (tid < E) {
        myid = nid[g * E + tid];
        m    = adj[g * (E * E) + tid * E];   // edge j -> node 0
    }
    if (tid < D) u_s[tid] = g_U[g * D + tid];

    // parallel compaction: warps 0 and 1 cover j = tid (j < 64 >= E)
    unsigned bw = __ballot_sync(0xffffffffu, m != 0);
    if (warp < 2 && lane == 0) bal[warp] = bw;
    __syncthreads();
    unsigned b0 = bal[0], b1 = bal[1];
    int cnt = __popc(b0) + __popc(b1);
    if (tid == 0) cnt_s = cnt;
    if (tid < E && m) {
        int pos = __popc((warp ? b0 : 0u)) +
                  __popc((warp ? b1 : b0) & ((1u << lane) - 1u));
        ids[pos] = myid;
    }
    __syncthreads();
    cnt = cnt_s;

    for (int q = tid; q < cnt * (D / 4); q += 128) {
        int r = q / 25, cc = q % 25;
        float4 v = reinterpret_cast<const float4*>(emb)[ids[r] * (D / 4) + cc];
        float* dst = &X[r * LD + cc * 4];
        dst[0] = v.x; dst[1] = v.y; dst[2] = v.z; dst[3] = v.w;
    }
    __syncthreads();

    if (tid < cnt) {
        const float* xr = &X[tid * LD];
        float s0 = 0.f, s1 = 0.f;
        #pragma unroll 10
        for (int d2 = 0; d2 < D; d2 += 2) {
            s0 = fmaf(xr[d2],     u_s[d2],     s0);
            s1 = fmaf(xr[d2 + 1], u_s[d2 + 1], s1);
        }
        sc[tid] = (s0 + s1) * 0.1f;          // /sqrt(H)
    }
    __syncthreads();

    float mx = -1e30f;
    for (int j = 0; j < cnt; ++j) mx = fmaxf(mx, sc[j]);
    if (tid < cnt) ps[tid] = __expf(sc[tid] - mx);
    __syncthreads();

    float S = 0.f;
    for (int j = 0; j < cnt; ++j) S += ps[j];
    float inv = 1.0f / S;

    if (tid < D) {
        float w = 0.f;
        for (int j = 0; j < cnt; ++j) w = fmaf(ps[j], X[j * LD + tid], w);
        g_wx[g * (2 * D) + tid]     = w * inv;
        g_wx[g * (2 * D) + D + tid] = X[tid];   // compact row 0 = x0
    }
}

// ---------------------------------------------------------------------------
// K4: out[g] = bvs + [w|x0] @ [Wv;Ws].  grid=400, 256 thr, K=200.
// Same 4-graphs-per-warp weight-sharing layout as K2.
// ---------------------------------------------------------------------------
__global__ __launch_bounds__(256) void k_out(float* __restrict__ out) {
    __shared__ float xs[8][2 * D];
    int tid = threadIdx.x, warp = tid >> 5, lane = tid & 31;
    int gbase = blockIdx.x * 8;

    for (int q = tid; q < 8 * (2 * D / 4); q += 256) {   // 400 float4, coalesced
        int r = q / 50, c = q % 50;
        reinterpret_cast<float4*>(&xs[r][0])[c] =
            reinterpret_cast<const float4*>(g_wx)[(gbase + r) * (2 * D / 4) + c];
    }
    __syncthreads();

    int gg = (warp >> 2) * 4;
    int ct = warp & 3;
    int gl = lane >> 3;
    int hg = lane & 7;
    int h0 = ct * 32 + hg * 4;
    const float* xr = xs[gg + gl];

    float4 acc = *reinterpret_cast<const float4*>(&g_bp[h0]);
    #pragma unroll 4
    for (int k = 0; k < 2 * D; ++k) {
        float  xv = xr[k];                                        // 4-way bcast
        float4 w  = *reinterpret_cast<const float4*>(&g_Wcp[k * NP + h0]);
        acc.x = fmaf(xv, w.x, acc.x); acc.y = fmaf(xv, w.y, acc.y);
        acc.z = fmaf(xv, w.z, acc.z); acc.w = fmaf(xv, w.w, acc.w);
    }
    if (h0 < H)
        *reinterpret_cast<float4*>(&out[(gbase + gg + gl) * H + h0]) = acc;
}

// ---------------------------------------------------------------------------
extern "C" void kernel_launch(void* const* d_in, const int* in_sizes, int n_in,
                              void* d_out, int out_size) {
    const int*   nid = (const int*)d_in[0];
    const int*   adj = (const int*)d_in[1];
    const float* emb = (const float*)d_in[2];
    const float* Wq  = (const float*)d_in[3];
    const float* bq  = (const float*)d_in[4];
    const float* Wk  = (const float*)d_in[5];
    // d_in[6] = bk: cancels in softmax (constant per-row shift)
    const float* Wv  = (const float*)d_in[7];
    const float* bv  = (const float*)d_in[8];
    const float* Ws  = (const float*)d_in[9];
    const float* bs  = (const float*)d_in[10];
    float* out = (float*)d_out;

    k_pre<<<3 * D + 1, 128>>>(Wq, bq, Wk, Wv, bv, Ws, bs);
    k_u<<<NG / 8, 256>>>(nid, emb);
    k_attn<<<NG, 128>>>(nid, adj, emb);
    k_out<<<NG / 8, 256>>>(out);
}